// round 12
// baseline (speedup 1.0000x reference)
#include <cuda_runtime.h>
#include <cstdint>
#include <math.h>

// ============================================================================
// VectorQuantizer — base ISA (mma.sync m16n8k32.s8 + ldmatrix + cp.async)
//   N = 262144 rows, D = 64, K = 1024 codes.
//   filter key  = int8 dot(xn_q, cn_q)   (bias ~const 0.5: dropped in filter)
//   exact key   = dot(xn, cn_k) - 0.5||cn_k||^2  (fp64, for flagged rows)
// ============================================================================

#define NROWS   262144
#define DIM     64
#define KCODES  1024
#define NQ      16777216
#define TILES   2048

// ---- device scratch ----
__device__ __align__(16) int8_t  g_b8[KCODES * DIM];   // quantized codebook s8
__device__ __align__(16) float   g_cnf[KCODES * DIM];  // normalized codebook fp32
__device__ double                g_biasd[KCODES];      // 0.5*||cn||^2 fp64
__device__ float                 g_partials[TILES];
__device__ unsigned int          g_cmax_u = 0;         // max |cn_i| (float bits)

// ---- smem layout (bytes) ----
#define SM_B     0          // 2 x (128 codes x 80B)    = 20480
#define SM_A     20480      // 128 rows x 80B           = 10240
#define SM_SX    30720      // 128 floats (row scale)   = 512
#define SM_RN    31232      // 128 floats (row norm)    = 512
#define SM_CAND  31744      // 128 x 16 uint16          = 4096
#define SM_LIST  35840      // 128 ints                 = 512
#define SM_ISW   36352      // 128 ints                 = 512
#define SM_CNT   36864      // 16
#define SM_RED   36880      // 32
#define SM_TOTAL 36912

// ---- PTX helpers ----
__device__ __forceinline__ void imma16832(int c[4], uint32_t a0, uint32_t a1,
                                          uint32_t a2, uint32_t a3,
                                          uint32_t b0, uint32_t b1) {
    asm volatile(
        "mma.sync.aligned.m16n8k32.row.col.s32.s8.s8.s32 "
        "{%0,%1,%2,%3}, {%4,%5,%6,%7}, {%8,%9}, {%0,%1,%2,%3};"
        : "+r"(c[0]), "+r"(c[1]), "+r"(c[2]), "+r"(c[3])
        : "r"(a0), "r"(a1), "r"(a2), "r"(a3), "r"(b0), "r"(b1));
}
__device__ __forceinline__ void ldm4(uint32_t addr, uint32_t& r0, uint32_t& r1,
                                     uint32_t& r2, uint32_t& r3) {
    asm volatile("ldmatrix.sync.aligned.m8n8.x4.shared.b16 {%0,%1,%2,%3}, [%4];"
                 : "=r"(r0), "=r"(r1), "=r"(r2), "=r"(r3) : "r"(addr));
}
__device__ __forceinline__ uint32_t smem_u32(const void* p) {
    uint32_t a;
    asm("{ .reg .u64 t; cvta.to.shared.u64 t, %1; cvt.u32.u64 %0, t; }"
        : "=r"(a) : "l"(p));
    return a;
}
__device__ __forceinline__ void cp16(uint32_t dst, const void* src) {
    asm volatile("cp.async.cg.shared.global [%0], [%1], 16;"
                 :: "r"(dst), "l"(src) : "memory");
}
__device__ __forceinline__ void cp_commit() {
    asm volatile("cp.async.commit_group;" ::: "memory");
}
__device__ __forceinline__ void cp_wait1() {
    asm volatile("cp.async.wait_group 1;" ::: "memory");
}
__device__ __forceinline__ void cp_wait0() {
    asm volatile("cp.async.wait_group 0;" ::: "memory");
}

// branch-free sorted top-4 insert (signed keys): K0 >= K1 >= K2 >= K3
__device__ __forceinline__ void ins4s(int K[4], int s) {
    int l0 = min(s, K[0]);  K[0] = max(s, K[0]);
    int l1 = min(l0, K[1]); K[1] = max(l0, K[1]);
    int l2 = min(l1, K[2]); K[2] = max(l1, K[2]);
    K[3] = max(l2, K[3]);
}

// ============================================================================
// Kernel 1a: normalize codebook, fp64 bias, global max|cn|
// ============================================================================
__global__ void vq_prep1(const float* __restrict__ cb) {
    int wid  = threadIdx.x >> 5;
    int lane = threadIdx.x & 31;
    int k = blockIdx.x * 8 + wid;
    float2 v = ((const float2*)(cb + (size_t)k * DIM))[lane];
    float s = v.x * v.x + v.y * v.y;
    #pragma unroll
    for (int o = 16; o > 0; o >>= 1) s += __shfl_xor_sync(0xffffffffu, s, o);
    float n = fmaxf(sqrtf(s), 1e-12f);
    float a0 = v.x / n, a1 = v.y / n;
    ((float2*)(g_cnf + (size_t)k * DIM))[lane] = make_float2(a0, a1);
    float am = fmaxf(fabsf(a0), fabsf(a1));
    double bd = (double)a0 * (double)a0 + (double)a1 * (double)a1;
    #pragma unroll
    for (int o = 16; o > 0; o >>= 1) {
        bd += __shfl_xor_sync(0xffffffffu, bd, o);
        am = fmaxf(am, __shfl_xor_sync(0xffffffffu, am, o));
    }
    if (lane == 0) {
        g_biasd[k] = 0.5 * bd;
        atomicMax(&g_cmax_u, __float_as_uint(am));
    }
}

// ============================================================================
// Kernel 1b: quantize codebook to s8 with global scale
// ============================================================================
__global__ void vq_prep2() {
    int wid  = threadIdx.x >> 5;
    int lane = threadIdx.x & 31;
    int k = blockIdx.x * 8 + wid;
    float sc = fminf(126.0f / __uint_as_float(g_cmax_u), 400.0f);
    float2 a = ((const float2*)(g_cnf + (size_t)k * DIM))[lane];
    int q0 = __float2int_rn(a.x * sc);
    int q1 = __float2int_rn(a.y * sc);
    ((uint16_t*)g_b8)[k * 32 + lane] =
        (uint16_t)((q0 & 0xFF) | ((q1 & 0xFF) << 8));
}

// ============================================================================
// Kernel 2: IMMA GEMM + argmax + fp64 rescue + outputs. 128 rows/CTA.
// ============================================================================
__global__ void __launch_bounds__(256, 3)
vq_main(const float* __restrict__ x, const float* __restrict__ cb,
        float* __restrict__ out) {
    extern __shared__ char smem[];
    const uint32_t sb = smem_u32(smem);
    const int tid  = threadIdx.x;
    const int wid  = tid >> 5;
    const int lane = tid & 31;
    const int row0 = blockIdx.x * 128;

    float*    sxs  = (float*)(smem + SM_SX);
    float*    rnsm = (float*)(smem + SM_RN);
    uint16_t* cand = (uint16_t*)(smem + SM_CAND);
    int*      list = (int*)(smem + SM_LIST);
    int*      cnt  = (int*)(smem + SM_CNT);
    int*      isw  = (int*)(smem + SM_ISW);
    float*    red  = (float*)(smem + SM_RED);

    if (tid == 0) *cnt = 0;
    const float sc_g = fminf(126.0f / __uint_as_float(g_cmax_u), 400.0f);

    // ---- prefetch B chunks 0,1 (s8: 128 codes x 64B, smem stride 80B) ----
    const int8_t* b8 = g_b8;
    #pragma unroll
    for (int pc = 0; pc < 2; pc++) {
        #pragma unroll
        for (int i = 0; i < 2; i++) {
            int idx = tid + i * 256;          // 0..511
            int r = idx >> 2, seg = idx & 3;
            cp16(sb + SM_B + pc * 10240 + r * 80 + seg * 16,
                 b8 + ((size_t)(pc * 128 + r)) * DIM + seg * 16);
        }
        cp_commit();
    }

    // ---- normalize + quantize rows -> s8 A (warp per row, gmem-direct) ----
    {
        const float2* x2 = (const float2*)(x + (size_t)row0 * DIM);
        #pragma unroll 4
        for (int j = 0; j < 16; j++) {
            int r = wid + 8 * j;              // 0..127
            float2 v = x2[r * 32 + lane];
            float s = v.x * v.x + v.y * v.y;
            float am = fmaxf(fabsf(v.x), fabsf(v.y));
            #pragma unroll
            for (int o = 16; o > 0; o >>= 1) {
                s += __shfl_xor_sync(0xffffffffu, s, o);
                am = fmaxf(am, __shfl_xor_sync(0xffffffffu, am, o));
            }
            float n = fmaxf(sqrtf(s), 1e-12f);
            float sx = fminf(126.0f * n / fmaxf(am, 1e-20f), 500.0f);
            float sxn = sx / n;
            int i0 = __float2int_rn(v.x * sxn);
            int i1 = __float2int_rn(v.y * sxn);
            *(uint16_t*)(smem + SM_A + r * 80 + lane * 2) =
                (uint16_t)((i0 & 0xFF) | ((i1 & 0xFF) << 8));
            if (lane == 0) { rnsm[r] = n; sxs[r] = sx; }
        }
    }
    __syncthreads();

    // ---- A fragments via ldmatrix (persist in registers) ----
    const int lr = lane & 7, m = lane >> 3;
    const int Rb = wid * 16;
    const uint32_t a_loff = (uint32_t)((Rb + lr + (m & 1) * 8) * 80 + (m >> 1) * 16);
    const uint32_t b_loff = (uint32_t)((lr + (m >> 1) * 8) * 80 + (m & 1) * 16);
    uint32_t af[8];
    ldm4(sb + SM_A + a_loff,      af[0], af[1], af[2], af[3]);  // k 0..31
    ldm4(sb + SM_A + a_loff + 32, af[4], af[5], af[6], af[7]);  // k 32..63

    // ---- main loop: 8 chunks of 128 codes, double-buffered ----
    int K0[4] = {INT_MIN, INT_MIN, INT_MIN, INT_MIN};
    int K1[4] = {INT_MIN, INT_MIN, INT_MIN, INT_MIN};
    const int c = lane & 3;

    #pragma unroll 1
    for (int ch = 0; ch < 8; ch++) {
        if (ch == 7) cp_wait0(); else cp_wait1();
        __syncthreads();
        const uint32_t Bb = sb + SM_B + (uint32_t)((ch & 1) * 10240) + b_loff;
        const int cb0 = ch * 128 + 2 * c;

        #pragma unroll
        for (int it = 0; it < 8; it++) {
            uint32_t p0, p1, p2, p3, q0, q1, q2, q3;
            ldm4(Bb + (uint32_t)(it * 1280),      p0, p1, p2, p3);  // k 0..31
            ldm4(Bb + (uint32_t)(it * 1280 + 32), q0, q1, q2, q3);  // k 32..63
            int acc0[4] = {0, 0, 0, 0};
            int acc1[4] = {0, 0, 0, 0};
            imma16832(acc0, af[0], af[1], af[2], af[3], p0, p1);
            imma16832(acc0, af[4], af[5], af[6], af[7], q0, q1);
            imma16832(acc1, af[0], af[1], af[2], af[3], p2, p3);
            imma16832(acc1, af[4], af[5], af[6], af[7], q2, q3);
            // packed signed keys -> top-4 per lane
            int col0 = cb0 + it * 16;
            int inv = 1023 - col0;
            ins4s(K0, acc0[0] * 1024 + inv);
            ins4s(K0, acc0[1] * 1024 + inv - 1);
            ins4s(K0, acc1[0] * 1024 + inv - 8);
            ins4s(K0, acc1[1] * 1024 + inv - 9);
            ins4s(K1, acc0[2] * 1024 + inv);
            ins4s(K1, acc0[3] * 1024 + inv - 1);
            ins4s(K1, acc1[2] * 1024 + inv - 8);
            ins4s(K1, acc1[3] * 1024 + inv - 9);
        }
        __syncthreads();
        if (ch < 6) {                          // prefetch chunk ch+2
            int pc = ch + 2;
            #pragma unroll
            for (int i = 0; i < 2; i++) {
                int idx = tid + i * 256;
                int r = idx >> 2, seg = idx & 3;
                cp16(sb + SM_B + (pc & 1) * 10240 + r * 80 + seg * 16,
                     b8 + ((size_t)(pc * 128 + r)) * DIM + seg * 16);
            }
            cp_commit();
        }
    }

    // ---- quad merge: row best / margin / candidate dump ----
    const int g = lane >> 2;
    #pragma unroll
    for (int h = 0; h < 2; h++) {
        int* K = h ? K1 : K0;
        int row = Rb + 8 * h + g;
        int bs = K[0];
        bs = max(bs, __shfl_xor_sync(0xffffffffu, bs, 1));
        bs = max(bs, __shfl_xor_sync(0xffffffffu, bs, 2));
        int s2 = (K[0] == bs) ? K[1] : K[0];
        s2 = max(s2, __shfl_xor_sync(0xffffffffu, s2, 1));
        s2 = max(s2, __shfl_xor_sync(0xffffffffu, s2, 2));
        #pragma unroll
        for (int j = 0; j < 4; j++)
            cand[row * 16 + 4 * c + j] = (uint16_t)(1023 - (K[j] & 1023));
        if (c == 0) {
            isw[row] = 1023 - (bs & 1023);
            int margin = (bs >> 10) - (s2 >> 10);
            int Tr = (int)(2.0f * (sxs[row] + sc_g)) + 2;
            if (margin < Tr) { int p = atomicAdd(cnt, 1); list[p] = row; }
        }
    }
    __syncthreads();

    // ---- fp64 rescue of flagged rows (16 candidates, warp per row) ----
    int nflag = *cnt;
    for (int e = wid; e < nflag; e += 8) {
        int row = list[e];
        double scv = -1e300; int kk = 0x7fffffff;
        if (lane < 16) {
            kk = (int)cand[row * 16 + lane];
            float rn = rnsm[row];
            const float* cp = g_cnf + (size_t)kk * DIM;
            const float* xr = x + (size_t)(row0 + row) * DIM;
            double d0 = 0, d1 = 0, d2 = 0, d3 = 0;
            #pragma unroll
            for (int j = 0; j < DIM; j += 4) {
                d0 += (double)(xr[j]     / rn) * (double)cp[j];
                d1 += (double)(xr[j + 1] / rn) * (double)cp[j + 1];
                d2 += (double)(xr[j + 2] / rn) * (double)cp[j + 2];
                d3 += (double)(xr[j + 3] / rn) * (double)cp[j + 3];
            }
            scv = ((d0 + d1) + (d2 + d3)) - g_biasd[kk];
        }
        #pragma unroll
        for (int off = 1; off <= 8; off <<= 1) {
            double os = __shfl_xor_sync(0xffffffffu, scv, off);
            int    oi = __shfl_xor_sync(0xffffffffu, kk, off);
            if (os > scv || (os == scv && oi < kk)) { scv = os; kk = oi; }
        }
        {
            double os = __shfl_xor_sync(0xffffffffu, scv, 16);
            int    oi = __shfl_xor_sync(0xffffffffu, kk, 16);
            if (os > scv || (os == scv && oi < kk)) { scv = os; kk = oi; }
        }
        if (lane == 0) isw[row] = kk;
    }
    __syncthreads();

    // ---- outputs: STE quantized + indices + partial SSE ----
    const float4* xg4 = (const float4*)(x + (size_t)row0 * DIM);
    float4*       og4 = (float4*)(out + (size_t)row0 * DIM);
    float sse = 0.f;
    #pragma unroll
    for (int i = 0; i < 8; i++) {
        int e4 = tid + i * 256;                // 0..2047 float4
        int r = e4 >> 4, c4 = e4 & 15;
        int k = isw[r];
        float4 xv = xg4[e4];
        float4 q  = *(const float4*)(cb + (size_t)k * DIM + c4 * 4);
        float4 o; float d;
        d = q.x - xv.x; sse += d * d; o.x = xv.x + d;
        d = q.y - xv.y; sse += d * d; o.y = xv.y + d;
        d = q.z - xv.z; sse += d * d; o.z = xv.z + d;
        d = q.w - xv.w; sse += d * d; o.w = xv.w + d;
        og4[e4] = o;
    }
    if (tid < 128) out[(size_t)NQ + 2 + row0 + tid] = (float)isw[tid];

    #pragma unroll
    for (int o = 16; o > 0; o >>= 1) sse += __shfl_xor_sync(0xffffffffu, sse, o);
    if (lane == 0) red[wid] = sse;
    __syncthreads();
    if (tid == 0) {
        float t = 0.f;
        #pragma unroll
        for (int w = 0; w < 8; w++) t += red[w];
        g_partials[blockIdx.x] = t;
    }
}

// ============================================================================
// Kernel 3: reduce partials -> both losses
// ============================================================================
__global__ void vq_fin(float* __restrict__ out) {
    __shared__ float red[8];
    int tid = threadIdx.x;
    float s = 0.f;
    #pragma unroll
    for (int i = 0; i < 8; i++) s += g_partials[tid + i * 256];
    #pragma unroll
    for (int o = 16; o > 0; o >>= 1) s += __shfl_xor_sync(0xffffffffu, s, o);
    if ((tid & 31) == 0) red[tid >> 5] = s;
    __syncthreads();
    if (tid == 0) {
        float t = 0.f;
        #pragma unroll
        for (int w = 0; w < 8; w++) t += red[w];
        float loss = t / 16777216.0f;
        out[NQ]     = loss;   // codebook_loss
        out[NQ + 1] = loss;   // commitment_loss
    }
}

// ============================================================================
extern "C" void kernel_launch(void* const* d_in, const int* in_sizes, int n_in,
                              void* d_out, int out_size) {
    const float* x;
    const float* cb;
    if (in_sizes[0] == NROWS * DIM) {
        x  = (const float*)d_in[0];
        cb = (const float*)d_in[1];
    } else {
        x  = (const float*)d_in[1];
        cb = (const float*)d_in[0];
    }
    float* out = (float*)d_out;

    cudaFuncSetAttribute(vq_main, cudaFuncAttributeMaxDynamicSharedMemorySize, SM_TOTAL);

    vq_prep1<<<128, 256>>>(cb);
    vq_prep2<<<128, 256>>>();
    vq_main<<<TILES, 256, SM_TOTAL>>>(x, cb, out);
    vq_fin<<<1, 256>>>(out);
}

// round 13
// speedup vs baseline: 1.2947x; 1.2947x over previous
#include <cuda_runtime.h>
#include <cuda_fp16.h>
#include <cstdint>
#include <math.h>

// ============================================================================
// VectorQuantizer — hybrid: fp16 HMMA (codes 128-1023) + fp32 FFMA (codes 0-127)
//   key = dot(xn, cn_k) + (2 - 0.5||cn_k||^2), packed-key argmax, fp64 rescue.
// ============================================================================

#define NROWS   262144
#define DIM     64
#define KCODES  1024
#define NQ      16777216
#define TILES   2048
#define THRESH  2e-3f

__device__ __align__(16) __half  g_bh[KCODES * DIM];
__device__ __align__(16) float   g_cnf[KCODES * DIM];
__device__ double                g_biasd[KCODES];
__device__ float                 g_biasf[KCODES];
__device__ float                 g_partials[TILES];

// ---- smem layout (bytes) ----
#define SM_B     0          // 2 x (128 codes x 144B) = 36864
#define SM_A     36864      // 128 x 144B             = 18432
#define SM_BIAS  55296      // 1024 f32 (2 - bias)    = 4096
#define SM_RN    59392      // 128 f32                = 512
#define SM_SK    59904      // 128 x 16 u32           = 8192
#define SM_CAND  68096      // 128 x 24 u16           = 6144
#define SM_LIST  74240      // 512
#define SM_CNT   74752      // 16
#define SM_ISW   74768      // 512
#define SM_RED   75280      // 32
#define SM_TOTAL 75312

__device__ __forceinline__ void mma16816(float c[4], const uint32_t a[4],
                                         uint32_t b0, uint32_t b1) {
    asm volatile(
        "mma.sync.aligned.m16n8k16.row.col.f32.f16.f16.f32 "
        "{%0,%1,%2,%3}, {%4,%5,%6,%7}, {%8,%9}, {%0,%1,%2,%3};"
        : "+f"(c[0]), "+f"(c[1]), "+f"(c[2]), "+f"(c[3])
        : "r"(a[0]), "r"(a[1]), "r"(a[2]), "r"(a[3]), "r"(b0), "r"(b1));
}
__device__ __forceinline__ void ldm4(uint32_t addr, uint32_t& r0, uint32_t& r1,
                                     uint32_t& r2, uint32_t& r3) {
    asm volatile("ldmatrix.sync.aligned.m8n8.x4.shared.b16 {%0,%1,%2,%3}, [%4];"
                 : "=r"(r0), "=r"(r1), "=r"(r2), "=r"(r3) : "r"(addr));
}
__device__ __forceinline__ uint32_t smem_u32(const void* p) {
    uint32_t a;
    asm("{ .reg .u64 t; cvta.to.shared.u64 t, %1; cvt.u32.u64 %0, t; }"
        : "=r"(a) : "l"(p));
    return a;
}
__device__ __forceinline__ void cp16(uint32_t dst, const void* src) {
    asm volatile("cp.async.cg.shared.global [%0], [%1], 16;"
                 :: "r"(dst), "l"(src) : "memory");
}
__device__ __forceinline__ void cp_commit() {
    asm volatile("cp.async.commit_group;" ::: "memory");
}
__device__ __forceinline__ void cp_wait1() {
    asm volatile("cp.async.wait_group 1;" ::: "memory");
}
__device__ __forceinline__ void cp_wait0() {
    asm volatile("cp.async.wait_group 0;" ::: "memory");
}

__device__ __forceinline__ uint32_t pkkey(float s, uint32_t invk) {
    return (__float_as_uint(s) & 0xFFFFFC00u) | invk;
}
__device__ __forceinline__ void ins2u(uint32_t K[2], uint32_t s) {
    uint32_t lo = umin(s, K[0]);
    K[0] = umax(s, K[0]);
    K[1] = umax(lo, K[1]);
}

// ============================================================================
__global__ void vq_prep(const float* __restrict__ cb) {
    int wid  = threadIdx.x >> 5;
    int lane = threadIdx.x & 31;
    int k = blockIdx.x * 8 + wid;
    float2 v = ((const float2*)(cb + (size_t)k * DIM))[lane];
    float s = v.x * v.x + v.y * v.y;
    #pragma unroll
    for (int o = 16; o > 0; o >>= 1) s += __shfl_xor_sync(0xffffffffu, s, o);
    float n = fmaxf(sqrtf(s), 1e-12f);
    float a0 = v.x / n, a1 = v.y / n;
    ((float2*)(g_cnf + (size_t)k * DIM))[lane] = make_float2(a0, a1);
    ((__half2*)(g_bh + (size_t)k * DIM))[lane] =
        __halves2half2(__float2half_rn(a0), __float2half_rn(a1));
    double bd = (double)a0 * (double)a0 + (double)a1 * (double)a1;
    #pragma unroll
    for (int o = 16; o > 0; o >>= 1) bd += __shfl_xor_sync(0xffffffffu, bd, o);
    if (lane == 0) { g_biasd[k] = 0.5 * bd; g_biasf[k] = (float)(0.5 * bd); }
}

// ============================================================================
__global__ void __launch_bounds__(256, 2)
vq_main(const float* __restrict__ x, const float* __restrict__ cb,
        float* __restrict__ out) {
    extern __shared__ char smem[];
    const uint32_t sb = smem_u32(smem);
    const int tid  = threadIdx.x;
    const int wid  = tid >> 5;
    const int lane = tid & 31;
    const int row0 = blockIdx.x * 128;

    float*    bsm  = (float*)(smem + SM_BIAS);
    float*    rnsm = (float*)(smem + SM_RN);
    uint32_t* skeys = (uint32_t*)(smem + SM_SK);
    uint16_t* cand = (uint16_t*)(smem + SM_CAND);
    int*      list = (int*)(smem + SM_LIST);
    int*      cnt  = (int*)(smem + SM_CNT);
    int*      isw  = (int*)(smem + SM_ISW);
    float*    red  = (float*)(smem + SM_RED);

    if (tid == 0) *cnt = 0;

    // ---- prefetch B chunks 1,2 ----
    const __half* bh = g_bh;
    #pragma unroll
    for (int pc = 1; pc <= 2; pc++) {
        #pragma unroll
        for (int i = 0; i < 4; i++) {
            int idx = tid + i * 256;
            int r = idx >> 3, seg = idx & 7;
            cp16(sb + SM_B + (pc & 1) * 18432 + r * 144 + seg * 16,
                 bh + ((size_t)(pc * 128 + r)) * DIM + seg * 8);
        }
        cp_commit();
    }

    #pragma unroll
    for (int i = 0; i < 4; i++) {
        int g0 = tid + i * 256;
        bsm[g0] = 2.0f - g_biasf[g0];
    }

    // ---- normalize rows -> fp16 A ----
    {
        const float2* x2 = (const float2*)(x + (size_t)row0 * DIM);
        #pragma unroll 4
        for (int j = 0; j < 16; j++) {
            int r = wid + 8 * j;
            float2 v = x2[r * 32 + lane];
            float s = v.x * v.x + v.y * v.y;
            #pragma unroll
            for (int o = 16; o > 0; o >>= 1)
                s += __shfl_xor_sync(0xffffffffu, s, o);
            float n = fmaxf(sqrtf(s), 1e-12f);
            if (lane == 0) rnsm[r] = n;
            *(__half2*)(smem + SM_A + r * 144 + lane * 4) =
                __halves2half2(__float2half_rn(v.x / n), __float2half_rn(v.y / n));
        }
    }
    __syncthreads();

    // ---- A fragments ----
    const int lr = lane & 7, m = lane >> 3;
    const int Rb = wid * 16;
    const uint32_t a_loff = (uint32_t)((lr + (m & 1) * 8) * 144 + (m >> 1) * 16);
    const uint32_t b_loff = (uint32_t)(((m >> 1) * 8 + lr) * 144 + (m & 1) * 16);
    uint32_t afr[4][4];
    #pragma unroll
    for (int ks = 0; ks < 4; ks++)
        ldm4(sb + SM_A + (uint32_t)(Rb * 144 + ks * 32) + a_loff,
             afr[ks][0], afr[ks][1], afr[ks][2], afr[ks][3]);

    // scalar-path row / codes
    const int rsc = ((wid & 3) << 5) + lane;          // 0..127
    const int csel = (wid >> 2) << 6;                 // 0 or 64
    const float invrn = 1.0f / rnsm[rsc];
    const float* xrow = x + (size_t)(row0 + rsc) * DIM;

    uint32_t K0[2] = {0, 0}, K1[2] = {0, 0};
    const int c = lane & 3;

    // ---- tensor chunks 1..7; scalar passes folded into ch 2..5 ----
    #pragma unroll 1
    for (int ch = 1; ch <= 7; ch++) {
        if (ch == 7) cp_wait0(); else cp_wait1();
        __syncthreads();
        const uint32_t Bb = sb + SM_B + (uint32_t)((ch & 1) * 18432) + b_loff;
        const int cb0 = ch * 128 + 2 * c;

        #pragma unroll
        for (int nbp = 0; nbp < 8; nbp++) {
            uint32_t bk[4][4];
            #pragma unroll
            for (int ks = 0; ks < 4; ks++)
                ldm4(Bb + (uint32_t)(nbp * 2304 + ks * 32),
                     bk[ks][0], bk[ks][1], bk[ks][2], bk[ks][3]);
            int col0 = cb0 + nbp * 16;
            float2 bb0 = *(const float2*)(bsm + col0);
            float2 bb1 = *(const float2*)(bsm + col0 + 8);
            float acc0[4] = {bb0.x, bb0.y, bb0.x, bb0.y};
            float acc1[4] = {bb1.x, bb1.y, bb1.x, bb1.y};
            #pragma unroll
            for (int ks = 0; ks < 4; ks++) {
                mma16816(acc0, afr[ks], bk[ks][0], bk[ks][1]);
                mma16816(acc1, afr[ks], bk[ks][2], bk[ks][3]);
            }
            uint32_t inv = (uint32_t)(1023 - col0);
            ins2u(K0, pkkey(acc0[0], inv));
            ins2u(K0, pkkey(acc0[1], inv - 1));
            ins2u(K0, pkkey(acc1[0], inv - 8));
            ins2u(K0, pkkey(acc1[1], inv - 9));
            ins2u(K1, pkkey(acc0[2], inv));
            ins2u(K1, pkkey(acc0[3], inv - 1));
            ins2u(K1, pkkey(acc1[2], inv - 8));
            ins2u(K1, pkkey(acc1[3], inv - 9));
        }

        // ---- scalar fp32 pass (codes 0..127 on FMA pipe) ----
        if (ch >= 2 && ch <= 5) {
            int p = ch - 2;
            int cbase = csel + (p << 4);              // 16 codes
            float acc[16];
            #pragma unroll
            for (int t = 0; t < 16; t++) acc[t] = bsm[cbase + t];
            #pragma unroll
            for (int db = 0; db < 4; db++) {
                const float4* x4 = (const float4*)(xrow + db * 16);
                float4 xa = x4[0], xb = x4[1], xc = x4[2], xd = x4[3];
                xa.x *= invrn; xa.y *= invrn; xa.z *= invrn; xa.w *= invrn;
                xb.x *= invrn; xb.y *= invrn; xb.z *= invrn; xb.w *= invrn;
                xc.x *= invrn; xc.y *= invrn; xc.z *= invrn; xc.w *= invrn;
                xd.x *= invrn; xd.y *= invrn; xd.z *= invrn; xd.w *= invrn;
                #pragma unroll
                for (int t = 0; t < 16; t++) {
                    const float4* c4 = (const float4*)(g_cnf
                        + (size_t)(cbase + t) * DIM + db * 16);
                    float4 p0 = c4[0], p1 = c4[1], p2 = c4[2], p3 = c4[3];
                    float a = acc[t];
                    a = fmaf(xa.x, p0.x, a); a = fmaf(xa.y, p0.y, a);
                    a = fmaf(xa.z, p0.z, a); a = fmaf(xa.w, p0.w, a);
                    a = fmaf(xb.x, p1.x, a); a = fmaf(xb.y, p1.y, a);
                    a = fmaf(xb.z, p1.z, a); a = fmaf(xb.w, p1.w, a);
                    a = fmaf(xc.x, p2.x, a); a = fmaf(xc.y, p2.y, a);
                    a = fmaf(xc.z, p2.z, a); a = fmaf(xc.w, p2.w, a);
                    a = fmaf(xd.x, p3.x, a); a = fmaf(xd.y, p3.y, a);
                    a = fmaf(xd.z, p3.z, a); a = fmaf(xd.w, p3.w, a);
                    acc[t] = a;
                }
            }
            uint32_t S[2] = {0, 0};
            #pragma unroll
            for (int t = 0; t < 16; t++)
                ins2u(S, pkkey(acc[t], (uint32_t)(1023 - (cbase + t))));
            int sid = p * 2 + (wid >> 2);             // 0..7
            skeys[rsc * 16 + sid * 2]     = S[0];
            skeys[rsc * 16 + sid * 2 + 1] = S[1];
        }

        __syncthreads();
        if (ch < 6) {
            int pc = ch + 2;
            #pragma unroll
            for (int i = 0; i < 4; i++) {
                int idx = tid + i * 256;
                int r = idx >> 3, seg = idx & 7;
                cp16(sb + SM_B + (pc & 1) * 18432 + r * 144 + seg * 16,
                     bh + ((size_t)(pc * 128 + r)) * DIM + seg * 8);
            }
            cp_commit();
        }
    }

    // ---- merge: tensor quad-merge + scalar keys fold ----
    const int g = lane >> 2;
    #pragma unroll
    for (int h = 0; h < 2; h++) {
        uint32_t* K = h ? K1 : K0;
        int row = Rb + 8 * h + g;
        uint32_t bs = K[0];
        bs = umax(bs, __shfl_xor_sync(0xffffffffu, bs, 1));
        bs = umax(bs, __shfl_xor_sync(0xffffffffu, bs, 2));
        uint32_t sc = (K[0] == bs) ? K[1] : K[0];
        sc = umax(sc, __shfl_xor_sync(0xffffffffu, sc, 1));
        sc = umax(sc, __shfl_xor_sync(0xffffffffu, sc, 2));
        cand[row * 24 + 2 * c]     = (uint16_t)(1023u - (K[0] & 1023u));
        cand[row * 24 + 2 * c + 1] = (uint16_t)(1023u - (K[1] & 1023u));
        if (c == 0) {
            const uint32_t* sk = skeys + row * 16;
            #pragma unroll
            for (int j = 0; j < 16; j++) {
                uint32_t k2 = sk[j];
                uint32_t lo = umin(k2, bs);
                bs = umax(k2, bs);
                sc = umax(lo, sc);
                cand[row * 24 + 8 + j] = (uint16_t)(1023u - (k2 & 1023u));
            }
            isw[row] = (int)(1023u - (bs & 1023u));
            float mf = __uint_as_float(bs & 0xFFFFFC00u)
                     - __uint_as_float(sc & 0xFFFFFC00u);
            if (mf < THRESH) { int p2 = atomicAdd(cnt, 1); list[p2] = row; }
        }
    }
    __syncthreads();

    // ---- fp64 rescue (24 candidates, warp per row) ----
    int nflag = *cnt;
    for (int e = wid; e < nflag; e += 8) {
        int row = list[e];
        double scv = -1e300; int kk = 0x7fffffff;
        if (lane < 24) {
            kk = (int)cand[row * 24 + lane];
            float rn = rnsm[row];
            const float* cp = g_cnf + (size_t)kk * DIM;
            const float* xr = x + (size_t)(row0 + row) * DIM;
            double d0 = 0, d1 = 0, d2 = 0, d3 = 0;
            #pragma unroll
            for (int j = 0; j < DIM; j += 4) {
                d0 += (double)(xr[j]     / rn) * (double)cp[j];
                d1 += (double)(xr[j + 1] / rn) * (double)cp[j + 1];
                d2 += (double)(xr[j + 2] / rn) * (double)cp[j + 2];
                d3 += (double)(xr[j + 3] / rn) * (double)cp[j + 3];
            }
            scv = ((d0 + d1) + (d2 + d3)) - g_biasd[kk];
        }
        #pragma unroll
        for (int off = 1; off <= 16; off <<= 1) {
            double os = __shfl_xor_sync(0xffffffffu, scv, off);
            int    oi = __shfl_xor_sync(0xffffffffu, kk, off);
            if (os > scv || (os == scv && oi < kk)) { scv = os; kk = oi; }
        }
        if (lane == 0) isw[row] = kk;
    }
    __syncthreads();

    // ---- outputs ----
    const float4* xg4 = (const float4*)(x + (size_t)row0 * DIM);
    float4*       og4 = (float4*)(out + (size_t)row0 * DIM);
    float sse = 0.f;
    #pragma unroll
    for (int i = 0; i < 8; i++) {
        int e4 = tid + i * 256;
        int r = e4 >> 4, c4 = e4 & 15;
        int k = isw[r];
        float4 xv = xg4[e4];
        float4 q  = *(const float4*)(cb + (size_t)k * DIM + c4 * 4);
        float4 o; float d;
        d = q.x - xv.x; sse += d * d; o.x = xv.x + d;
        d = q.y - xv.y; sse += d * d; o.y = xv.y + d;
        d = q.z - xv.z; sse += d * d; o.z = xv.z + d;
        d = q.w - xv.w; sse += d * d; o.w = xv.w + d;
        og4[e4] = o;
    }
    if (tid < 128) out[(size_t)NQ + 2 + row0 + tid] = (float)isw[tid];

    #pragma unroll
    for (int o = 16; o > 0; o >>= 1) sse += __shfl_xor_sync(0xffffffffu, sse, o);
    if (lane == 0) red[wid] = sse;
    __syncthreads();
    if (tid == 0) {
        float t = 0.f;
        #pragma unroll
        for (int w = 0; w < 8; w++) t += red[w];
        g_partials[blockIdx.x] = t;
    }
}

// ============================================================================
__global__ void vq_fin(float* __restrict__ out) {
    __shared__ float red[8];
    int tid = threadIdx.x;
    float s = 0.f;
    #pragma unroll
    for (int i = 0; i < 8; i++) s += g_partials[tid + i * 256];
    #pragma unroll
    for (int o = 16; o > 0; o >>= 1) s += __shfl_xor_sync(0xffffffffu, s, o);
    if ((tid & 31) == 0) red[tid >> 5] = s;
    __syncthreads();
    if (tid == 0) {
        float t = 0.f;
        #pragma unroll
        for (int w = 0; w < 8; w++) t += red[w];
        float loss = t / 16777216.0f;
        out[NQ]     = loss;
        out[NQ + 1] = loss;
    }
}

// ============================================================================
extern "C" void kernel_launch(void* const* d_in, const int* in_sizes, int n_in,
                              void* d_out, int out_size) {
    const float* x;
    const float* cb;
    if (in_sizes[0] == NROWS * DIM) {
        x  = (const float*)d_in[0];
        cb = (const float*)d_in[1];
    } else {
        x  = (const float*)d_in[1];
        cb = (const float*)d_in[0];
    }
    float* out = (float*)d_out;

    cudaFuncSetAttribute(vq_main, cudaFuncAttributeMaxDynamicSharedMemorySize, SM_TOTAL);

    vq_prep<<<128, 256>>>(cb);
    vq_main<<<TILES, 256, SM_TOTAL>>>(x, cb, out);
    vq_fin<<<1, 256>>>(out);
}

// round 14
// speedup vs baseline: 2.5082x; 1.9373x over previous
#include <cuda_runtime.h>
#include <cuda_fp16.h>
#include <cstdint>
#include <math.h>

// ============================================================================
// VectorQuantizer — base-target ISA (mma.sync m16n8k16 + ldmatrix + cp.async)
//   N = 262144 rows, D = 64, K = 1024 codes.
//   filter key = dot(xn, cn_k) + 2.0  (||cn||=1 so bias is constant to 5e-8;
//                exact per-k bias retained in the fp64 rescue)
//   fp16 HMMA scores, branch-free packed-key top-2, fp64 rescue, persistent grid.
// ============================================================================

#define NROWS   262144
#define DIM     64
#define KCODES  1024
#define NQ      16777216
#define NTILES  2048
#define NWORK   444                // 148 SMs x 3 residents
#define THRESH  2e-3f

// ---- device scratch ----
__device__ __align__(16) __half  g_bh[KCODES * DIM];   // normalized codebook fp16
__device__ __align__(16) float   g_cnf[KCODES * DIM];  // normalized codebook fp32
__device__ double                g_biasd[KCODES];      // 0.5*||cn||^2 fp64
__device__ float                 g_partials[NTILES];

// ---- smem layout (bytes) ----
#define SM_B     0          // 2 x (128 codes x 144B)   = 36864
#define SM_A     36864      // 128 rows x 144B          = 18432
#define SM_RN    55296      // 128 floats               = 512
#define SM_CAND  55808      // 128 x 8 uint16           = 2048
#define SM_LIST  57856      // 128 ints                 = 512
#define SM_CNT   58368      // 16
#define SM_ISW   58384      // 128 ints                 = 512
#define SM_RED   58896      // 32
#define SM_TOTAL 58928

// ---- PTX helpers ----
__device__ __forceinline__ void mma16816(float c[4], const uint32_t a[4],
                                         uint32_t b0, uint32_t b1) {
    asm volatile(
        "mma.sync.aligned.m16n8k16.row.col.f32.f16.f16.f32 "
        "{%0,%1,%2,%3}, {%4,%5,%6,%7}, {%8,%9}, {%0,%1,%2,%3};"
        : "+f"(c[0]), "+f"(c[1]), "+f"(c[2]), "+f"(c[3])
        : "r"(a[0]), "r"(a[1]), "r"(a[2]), "r"(a[3]), "r"(b0), "r"(b1));
}
__device__ __forceinline__ void ldm4(uint32_t addr, uint32_t& r0, uint32_t& r1,
                                     uint32_t& r2, uint32_t& r3) {
    asm volatile("ldmatrix.sync.aligned.m8n8.x4.shared.b16 {%0,%1,%2,%3}, [%4];"
                 : "=r"(r0), "=r"(r1), "=r"(r2), "=r"(r3) : "r"(addr));
}
__device__ __forceinline__ uint32_t smem_u32(const void* p) {
    uint32_t a;
    asm("{ .reg .u64 t; cvta.to.shared.u64 t, %1; cvt.u32.u64 %0, t; }"
        : "=r"(a) : "l"(p));
    return a;
}
__device__ __forceinline__ void cp16(uint32_t dst, const void* src) {
    asm volatile("cp.async.cg.shared.global [%0], [%1], 16;"
                 :: "r"(dst), "l"(src) : "memory");
}
__device__ __forceinline__ void cp_commit() {
    asm volatile("cp.async.commit_group;" ::: "memory");
}
__device__ __forceinline__ void cp_wait1() {
    asm volatile("cp.async.wait_group 1;" ::: "memory");
}
__device__ __forceinline__ void cp_wait0() {
    asm volatile("cp.async.wait_group 0;" ::: "memory");
}

// packed key: upper 22 bits = (2.0 + score) bits, low 10 bits = (1023 - col)
__device__ __forceinline__ uint32_t pkkey(float s, uint32_t invk) {
    return (__float_as_uint(s) & 0xFFFFFC00u) | invk;   // single LOP3
}
// branch-free sorted top-2 insert: K0 >= K1 (3 min/max ops)
__device__ __forceinline__ void ins2u(uint32_t K[2], uint32_t s) {
    uint32_t lo = umin(s, K[0]);
    K[0] = umax(s, K[0]);
    K[1] = umax(lo, K[1]);
}

// ============================================================================
// Kernel 1: codebook prep — warp per code
// ============================================================================
__global__ void vq_prep(const float* __restrict__ cb) {
    int wid  = threadIdx.x >> 5;
    int lane = threadIdx.x & 31;
    int k = blockIdx.x * 8 + wid;
    float2 v = ((const float2*)(cb + (size_t)k * DIM))[lane];
    float s = v.x * v.x + v.y * v.y;
    #pragma unroll
    for (int o = 16; o > 0; o >>= 1) s += __shfl_xor_sync(0xffffffffu, s, o);
    float n = fmaxf(sqrtf(s), 1e-12f);
    float a0 = v.x / n, a1 = v.y / n;
    ((float2*)(g_cnf + (size_t)k * DIM))[lane] = make_float2(a0, a1);
    ((__half2*)(g_bh + (size_t)k * DIM))[lane] =
        __halves2half2(__float2half_rn(a0), __float2half_rn(a1));
    double bd = (double)a0 * (double)a0 + (double)a1 * (double)a1;
    #pragma unroll
    for (int o = 16; o > 0; o >>= 1) bd += __shfl_xor_sync(0xffffffffu, bd, o);
    if (lane == 0) g_biasd[k] = 0.5 * bd;
}

// ============================================================================
// Kernel 2: persistent GEMM + argmax + rescue + outputs. 128 rows/tile.
// ============================================================================
__global__ void __launch_bounds__(256, 3)
vq_main(const float* __restrict__ x, const float* __restrict__ cb,
        float* __restrict__ out) {
    extern __shared__ char smem[];
    const uint32_t sb = smem_u32(smem);
    const int tid  = threadIdx.x;
    const int wid  = tid >> 5;
    const int lane = tid & 31;

    float*    rnsm = (float*)(smem + SM_RN);
    uint16_t* cand = (uint16_t*)(smem + SM_CAND);
    int*      list = (int*)(smem + SM_LIST);
    int*      cnt  = (int*)(smem + SM_CNT);
    int*      isw  = (int*)(smem + SM_ISW);
    float*    red  = (float*)(smem + SM_RED);

    const __half* bh = g_bh;
    const int lr = lane & 7, m = lane >> 3;
    const int Rb = wid * 16;
    const uint32_t a_loff = (uint32_t)((lr + (m & 1) * 8) * 144 + (m >> 1) * 16);
    const uint32_t b_loff = (uint32_t)(((m >> 1) * 8 + lr) * 144 + (m & 1) * 16);
    const int c = lane & 3;
    const int g = lane >> 2;

    for (int tile = blockIdx.x; tile < NTILES; tile += NWORK) {
        const int row0 = tile * 128;
        __syncthreads();                       // previous tile fully done
        if (tid == 0) *cnt = 0;

        // ---- prefetch B chunks 0,1 ----
        #pragma unroll
        for (int pc = 0; pc < 2; pc++) {
            #pragma unroll
            for (int i = 0; i < 4; i++) {
                int idx = tid + i * 256;
                int r = idx >> 3, seg = idx & 7;
                cp16(sb + SM_B + pc * 18432 + r * 144 + seg * 16,
                     bh + ((size_t)(pc * 128 + r)) * DIM + seg * 8);
            }
            cp_commit();
        }

        // ---- normalize rows -> fp16 A (warp per row, gmem-direct) ----
        {
            const float2* x2 = (const float2*)(x + (size_t)row0 * DIM);
            #pragma unroll 4
            for (int j = 0; j < 16; j++) {
                int r = wid + 8 * j;
                float2 v = x2[r * 32 + lane];
                float s = v.x * v.x + v.y * v.y;
                #pragma unroll
                for (int o = 16; o > 0; o >>= 1)
                    s += __shfl_xor_sync(0xffffffffu, s, o);
                float n = fmaxf(sqrtf(s), 1e-12f);
                if (lane == 0) rnsm[r] = n;
                *(__half2*)(smem + SM_A + r * 144 + lane * 4) =
                    __halves2half2(__float2half_rn(v.x / n),
                                   __float2half_rn(v.y / n));
            }
        }
        __syncthreads();

        // ---- A fragments via ldmatrix ----
        uint32_t afr[4][4];
        #pragma unroll
        for (int ks = 0; ks < 4; ks++)
            ldm4(sb + SM_A + (uint32_t)(Rb * 144 + ks * 32) + a_loff,
                 afr[ks][0], afr[ks][1], afr[ks][2], afr[ks][3]);

        uint32_t K0[2] = {0, 0}, K1[2] = {0, 0};

        // ---- main loop: 8 chunks of 128 codes, double-buffered ----
        #pragma unroll 1
        for (int ch = 0; ch < 8; ch++) {
            if (ch == 7) cp_wait0(); else cp_wait1();
            __syncthreads();
            const uint32_t Bb = sb + SM_B + (uint32_t)((ch & 1) * 18432) + b_loff;
            const int cb0 = ch * 128 + 2 * c;

            #pragma unroll
            for (int nbp = 0; nbp < 8; nbp++) {
                uint32_t bk[4][4];
                #pragma unroll
                for (int ks = 0; ks < 4; ks++)
                    ldm4(Bb + (uint32_t)(nbp * 2304 + ks * 32),
                         bk[ks][0], bk[ks][1], bk[ks][2], bk[ks][3]);
                float acc0[4] = {2.0f, 2.0f, 2.0f, 2.0f};
                float acc1[4] = {2.0f, 2.0f, 2.0f, 2.0f};
                #pragma unroll
                for (int ks = 0; ks < 4; ks++) {
                    mma16816(acc0, afr[ks], bk[ks][0], bk[ks][1]);
                    mma16816(acc1, afr[ks], bk[ks][2], bk[ks][3]);
                }
                int col0 = cb0 + nbp * 16;
                uint32_t inv = (uint32_t)(1023 - col0);
                ins2u(K0, pkkey(acc0[0], inv));
                ins2u(K0, pkkey(acc0[1], inv - 1));
                ins2u(K0, pkkey(acc1[0], inv - 8));
                ins2u(K0, pkkey(acc1[1], inv - 9));
                ins2u(K1, pkkey(acc0[2], inv));
                ins2u(K1, pkkey(acc0[3], inv - 1));
                ins2u(K1, pkkey(acc1[2], inv - 8));
                ins2u(K1, pkkey(acc1[3], inv - 9));
            }
            __syncthreads();
            if (ch < 6) {
                int pc = ch + 2;
                #pragma unroll
                for (int i = 0; i < 4; i++) {
                    int idx = tid + i * 256;
                    int r = idx >> 3, seg = idx & 7;
                    cp16(sb + SM_B + (pc & 1) * 18432 + r * 144 + seg * 16,
                         bh + ((size_t)(pc * 128 + r)) * DIM + seg * 8);
                }
                cp_commit();
            }
        }

        // ---- quad merge: row best / margin / candidate dump ----
        #pragma unroll
        for (int h = 0; h < 2; h++) {
            uint32_t* K = h ? K1 : K0;
            int row = Rb + 8 * h + g;
            uint32_t bs = K[0];
            bs = umax(bs, __shfl_xor_sync(0xffffffffu, bs, 1));
            bs = umax(bs, __shfl_xor_sync(0xffffffffu, bs, 2));
            uint32_t sc = (K[0] == bs) ? K[1] : K[0];
            sc = umax(sc, __shfl_xor_sync(0xffffffffu, sc, 1));
            sc = umax(sc, __shfl_xor_sync(0xffffffffu, sc, 2));
            cand[row * 8 + 2 * c]     = (uint16_t)(1023u - (K[0] & 1023u));
            cand[row * 8 + 2 * c + 1] = (uint16_t)(1023u - (K[1] & 1023u));
            if (c == 0) {
                isw[row] = (int)(1023u - (bs & 1023u));
                float mf = __uint_as_float(bs & 0xFFFFFC00u)
                         - __uint_as_float(sc & 0xFFFFFC00u);
                if (mf < THRESH) { int p = atomicAdd(cnt, 1); list[p] = row; }
            }
        }
        __syncthreads();

        // ---- fp64 rescue of tight rows (8 candidates, warp per row) ----
        int nflag = *cnt;
        for (int e = wid; e < nflag; e += 8) {
            int row = list[e];
            double scv = -1e300; int kk = 0x7fffffff;
            if (lane < 8) {
                kk = (int)cand[row * 8 + lane];
                float rn = rnsm[row];
                const float* cp = g_cnf + (size_t)kk * DIM;
                const float* xr = x + (size_t)(row0 + row) * DIM;
                double d0 = 0, d1 = 0, d2 = 0, d3 = 0;
                #pragma unroll
                for (int j = 0; j < DIM; j += 4) {
                    d0 += (double)(xr[j]     / rn) * (double)cp[j];
                    d1 += (double)(xr[j + 1] / rn) * (double)cp[j + 1];
                    d2 += (double)(xr[j + 2] / rn) * (double)cp[j + 2];
                    d3 += (double)(xr[j + 3] / rn) * (double)cp[j + 3];
                }
                scv = ((d0 + d1) + (d2 + d3)) - g_biasd[kk];
            }
            #pragma unroll
            for (int off = 1; off <= 8; off <<= 1) {
                double os = __shfl_xor_sync(0xffffffffu, scv, off);
                int    oi = __shfl_xor_sync(0xffffffffu, kk, off);
                if (os > scv || (os == scv && oi < kk)) { scv = os; kk = oi; }
            }
            if (lane == 0) isw[row] = kk;
        }
        __syncthreads();

        // ---- outputs: STE quantized + indices + partial SSE ----
        const float4* xg4 = (const float4*)(x + (size_t)row0 * DIM);
        float4*       og4 = (float4*)(out + (size_t)row0 * DIM);
        float sse = 0.f;
        #pragma unroll
        for (int i = 0; i < 8; i++) {
            int e4 = tid + i * 256;
            int r = e4 >> 4, c4 = e4 & 15;
            int k = isw[r];
            float4 xv = xg4[e4];
            float4 q  = *(const float4*)(cb + (size_t)k * DIM + c4 * 4);
            float4 o; float d;
            d = q.x - xv.x; sse += d * d; o.x = xv.x + d;
            d = q.y - xv.y; sse += d * d; o.y = xv.y + d;
            d = q.z - xv.z; sse += d * d; o.z = xv.z + d;
            d = q.w - xv.w; sse += d * d; o.w = xv.w + d;
            og4[e4] = o;
        }
        if (tid < 128) out[(size_t)NQ + 2 + row0 + tid] = (float)isw[tid];

        #pragma unroll
        for (int o = 16; o > 0; o >>= 1)
            sse += __shfl_xor_sync(0xffffffffu, sse, o);
        if (lane == 0) red[wid] = sse;
        __syncthreads();
        if (tid == 0) {
            float t = 0.f;
            #pragma unroll
            for (int w = 0; w < 8; w++) t += red[w];
            g_partials[tile] = t;
        }
    }
}

// ============================================================================
// Kernel 3: reduce partials -> both losses
// ============================================================================
__global__ void vq_fin(float* __restrict__ out) {
    __shared__ float red[8];
    int tid = threadIdx.x;
    float s = 0.f;
    #pragma unroll
    for (int i = 0; i < 8; i++) s += g_partials[tid + i * 256];
    #pragma unroll
    for (int o = 16; o > 0; o >>= 1) s += __shfl_xor_sync(0xffffffffu, s, o);
    if ((tid & 31) == 0) red[tid >> 5] = s;
    __syncthreads();
    if (tid == 0) {
        float t = 0.f;
        #pragma unroll
        for (int w = 0; w < 8; w++) t += red[w];
        float loss = t / 16777216.0f;
        out[NQ]     = loss;   // codebook_loss
        out[NQ + 1] = loss;   // commitment_loss
    }
}

// ============================================================================
extern "C" void kernel_launch(void* const* d_in, const int* in_sizes, int n_in,
                              void* d_out, int out_size) {
    const float* x;
    const float* cb;
    if (in_sizes[0] == NROWS * DIM) {
        x  = (const float*)d_in[0];
        cb = (const float*)d_in[1];
    } else {
        x  = (const float*)d_in[1];
        cb = (const float*)d_in[0];
    }
    float* out = (float*)d_out;

    cudaFuncSetAttribute(vq_main, cudaFuncAttributeMaxDynamicSharedMemorySize, SM_TOTAL);

    vq_prep<<<128, 256>>>(cb);
    vq_main<<<NWORK, 256, SM_TOTAL>>>(x, cb, out);
    vq_fin<<<1, 256>>>(out);
}

// round 15
// speedup vs baseline: 3.1206x; 1.2441x over previous
#include <cuda_runtime.h>
#include <cuda_fp16.h>
#include <cstdint>
#include <math.h>

// ============================================================================
// VectorQuantizer — base-target ISA (mma.sync m16n8k16 + ldmatrix + cp.async)
//   N = 262144 rows, D = 64, K = 1024 codes.
//   filter key = dot(xn, cn_k) + 2.0   (||cn||=1: bias constant to 5e-8;
//                exact per-k bias retained in the fp64 rescue)
//   fp16 HMMA scores, branch-free packed-key top-2, fp64 rescue.
//   R15: smem overlay + interleaved ldm/mma -> 4 CTAs/SM (64-reg cap).
// ============================================================================

#define NROWS   262144
#define DIM     64
#define KCODES  1024
#define NQ      16777216
#define TILES   2048
#define THRESH  2e-3f

// ---- device scratch ----
__device__ __align__(16) __half  g_bh[KCODES * DIM];   // normalized codebook fp16
__device__ __align__(16) float   g_cnf[KCODES * DIM];  // normalized codebook fp32
__device__ double                g_biasd[KCODES];      // 0.5*||cn||^2 fp64
__device__ float                 g_partials[TILES];

// ---- smem layout (bytes); cand/list/isw/red OVERLAY the dead A buffer ----
#define SM_B     0          // 2 x (128 codes x 144B)   = 36864
#define SM_A     36864      // 128 rows x 144B          = 18432 (dead post-ldm)
#define SM_CAND  36864      //   overlay: 128 x 8 u16   = 2048
#define SM_LIST  38912      //   overlay: 128 ints      = 512
#define SM_ISW   39424      //   overlay: 128 ints      = 512
#define SM_RED   39936      //   overlay: 8 floats      = 32
#define SM_RN    55296      // 128 floats               = 512
#define SM_CNT   55808      // 16
#define SM_TOTAL 55824

// ---- PTX helpers ----
__device__ __forceinline__ void mma16816(float c[4], const uint32_t a[4],
                                         uint32_t b0, uint32_t b1) {
    asm volatile(
        "mma.sync.aligned.m16n8k16.row.col.f32.f16.f16.f32 "
        "{%0,%1,%2,%3}, {%4,%5,%6,%7}, {%8,%9}, {%0,%1,%2,%3};"
        : "+f"(c[0]), "+f"(c[1]), "+f"(c[2]), "+f"(c[3])
        : "r"(a[0]), "r"(a[1]), "r"(a[2]), "r"(a[3]), "r"(b0), "r"(b1));
}
__device__ __forceinline__ void ldm4(uint32_t addr, uint32_t& r0, uint32_t& r1,
                                     uint32_t& r2, uint32_t& r3) {
    asm volatile("ldmatrix.sync.aligned.m8n8.x4.shared.b16 {%0,%1,%2,%3}, [%4];"
                 : "=r"(r0), "=r"(r1), "=r"(r2), "=r"(r3) : "r"(addr));
}
__device__ __forceinline__ uint32_t smem_u32(const void* p) {
    uint32_t a;
    asm("{ .reg .u64 t; cvta.to.shared.u64 t, %1; cvt.u32.u64 %0, t; }"
        : "=r"(a) : "l"(p));
    return a;
}
__device__ __forceinline__ void cp16(uint32_t dst, const void* src) {
    asm volatile("cp.async.cg.shared.global [%0], [%1], 16;"
                 :: "r"(dst), "l"(src) : "memory");
}
__device__ __forceinline__ void cp_commit() {
    asm volatile("cp.async.commit_group;" ::: "memory");
}
__device__ __forceinline__ void cp_wait1() {
    asm volatile("cp.async.wait_group 1;" ::: "memory");
}
__device__ __forceinline__ void cp_wait0() {
    asm volatile("cp.async.wait_group 0;" ::: "memory");
}

// packed key: upper 22 bits = (2.0 + score) bits, low 10 bits = (1023 - col)
__device__ __forceinline__ uint32_t pkkey(float s, uint32_t invk) {
    return (__float_as_uint(s) & 0xFFFFFC00u) | invk;   // single LOP3
}
// branch-free sorted top-2 insert: K0 >= K1 (3 min/max ops)
__device__ __forceinline__ void ins2u(uint32_t K[2], uint32_t s) {
    uint32_t lo = umin(s, K[0]);
    K[0] = umax(s, K[0]);
    K[1] = umax(lo, K[1]);
}

// ============================================================================
// Kernel 1: codebook prep — warp per code
// ============================================================================
__global__ void vq_prep(const float* __restrict__ cb) {
    int wid  = threadIdx.x >> 5;
    int lane = threadIdx.x & 31;
    int k = blockIdx.x * 8 + wid;
    float2 v = ((const float2*)(cb + (size_t)k * DIM))[lane];
    float s = v.x * v.x + v.y * v.y;
    #pragma unroll
    for (int o = 16; o > 0; o >>= 1) s += __shfl_xor_sync(0xffffffffu, s, o);
    float n = fmaxf(sqrtf(s), 1e-12f);
    float a0 = v.x / n, a1 = v.y / n;
    ((float2*)(g_cnf + (size_t)k * DIM))[lane] = make_float2(a0, a1);
    ((__half2*)(g_bh + (size_t)k * DIM))[lane] =
        __halves2half2(__float2half_rn(a0), __float2half_rn(a1));
    double bd = (double)a0 * (double)a0 + (double)a1 * (double)a1;
    #pragma unroll
    for (int o = 16; o > 0; o >>= 1) bd += __shfl_xor_sync(0xffffffffu, bd, o);
    if (lane == 0) g_biasd[k] = 0.5 * bd;
}

// ============================================================================
// Kernel 2: GEMM + argmax + rescue + outputs. 128 rows/CTA, 8 warps x m16.
// ============================================================================
__global__ void __launch_bounds__(256, 4)
vq_main(const float* __restrict__ x, const float* __restrict__ cb,
        float* __restrict__ out) {
    extern __shared__ char smem[];
    const uint32_t sb = smem_u32(smem);
    const int tid  = threadIdx.x;
    const int wid  = tid >> 5;
    const int lane = tid & 31;
    const int row0 = blockIdx.x * 128;

    float*    rnsm = (float*)(smem + SM_RN);
    uint16_t* cand = (uint16_t*)(smem + SM_CAND);
    int*      list = (int*)(smem + SM_LIST);
    int*      cnt  = (int*)(smem + SM_CNT);
    int*      isw  = (int*)(smem + SM_ISW);
    float*    red  = (float*)(smem + SM_RED);

    if (tid == 0) *cnt = 0;

    // ---- prefetch B chunks 0,1 via cp.async ----
    const __half* bh = g_bh;
    #pragma unroll
    for (int pc = 0; pc < 2; pc++) {
        #pragma unroll
        for (int i = 0; i < 4; i++) {
            int idx = tid + i * 256;          // 0..1023
            int r = idx >> 3, seg = idx & 7;
            cp16(sb + SM_B + pc * 18432 + r * 144 + seg * 16,
                 bh + ((size_t)(pc * 128 + r)) * DIM + seg * 8);
        }
        cp_commit();
    }

    // ---- normalize rows -> fp16 A (warp per row, gmem-direct) ----
    {
        const float2* x2 = (const float2*)(x + (size_t)row0 * DIM);
        #pragma unroll 4
        for (int j = 0; j < 16; j++) {
            int r = wid + 8 * j;              // 0..127
            float2 v = x2[r * 32 + lane];
            float s = v.x * v.x + v.y * v.y;
            #pragma unroll
            for (int o = 16; o > 0; o >>= 1)
                s += __shfl_xor_sync(0xffffffffu, s, o);
            float n = fmaxf(sqrtf(s), 1e-12f);
            if (lane == 0) rnsm[r] = n;
            *(__half2*)(smem + SM_A + r * 144 + lane * 4) =
                __halves2half2(__float2half_rn(v.x / n), __float2half_rn(v.y / n));
        }
    }
    __syncthreads();

    // ---- A fragments via ldmatrix (persist in registers) ----
    const int lr = lane & 7, m = lane >> 3;
    const int Rb = wid * 16;
    const uint32_t a_loff = (uint32_t)((lr + (m & 1) * 8) * 144 + (m >> 1) * 16);
    const uint32_t b_loff = (uint32_t)(((m >> 1) * 8 + lr) * 144 + (m & 1) * 16);
    uint32_t afr[4][4];
    #pragma unroll
    for (int ks = 0; ks < 4; ks++)
        ldm4(sb + SM_A + (uint32_t)(Rb * 144 + ks * 32) + a_loff,
             afr[ks][0], afr[ks][1], afr[ks][2], afr[ks][3]);
    __syncthreads();                           // A buffer now dead (overlay ok)

    // ---- main loop: 8 chunks of 128 codes, double-buffered ----
    uint32_t K0[2] = {0, 0}, K1[2] = {0, 0};
    const int c = lane & 3;

    #pragma unroll 1
    for (int ch = 0; ch < 8; ch++) {
        if (ch == 7) cp_wait0(); else cp_wait1();
        __syncthreads();
        const uint32_t Bb = sb + SM_B + (uint32_t)((ch & 1) * 18432) + b_loff;
        const int cb0 = ch * 128 + 2 * c;

        #pragma unroll
        for (int nbp = 0; nbp < 8; nbp++) {
            float acc0[4] = {2.0f, 2.0f, 2.0f, 2.0f};
            float acc1[4] = {2.0f, 2.0f, 2.0f, 2.0f};
            #pragma unroll
            for (int ks = 0; ks < 4; ks++) {
                uint32_t b0, b1, b2, b3;
                ldm4(Bb + (uint32_t)(nbp * 2304 + ks * 32), b0, b1, b2, b3);
                mma16816(acc0, afr[ks], b0, b1);
                mma16816(acc1, afr[ks], b2, b3);
            }
            // branch-free epilogue: packed key -> top-2 (4 alu ops/score)
            int col0 = cb0 + nbp * 16;
            uint32_t inv = (uint32_t)(1023 - col0);
            ins2u(K0, pkkey(acc0[0], inv));
            ins2u(K0, pkkey(acc0[1], inv - 1));
            ins2u(K0, pkkey(acc1[0], inv - 8));
            ins2u(K0, pkkey(acc1[1], inv - 9));
            ins2u(K1, pkkey(acc0[2], inv));
            ins2u(K1, pkkey(acc0[3], inv - 1));
            ins2u(K1, pkkey(acc1[2], inv - 8));
            ins2u(K1, pkkey(acc1[3], inv - 9));
        }
        __syncthreads();
        if (ch < 6) {                          // prefetch chunk ch+2
            int pc = ch + 2;
            #pragma unroll
            for (int i = 0; i < 4; i++) {
                int idx = tid + i * 256;
                int r = idx >> 3, seg = idx & 7;
                cp16(sb + SM_B + (pc & 1) * 18432 + r * 144 + seg * 16,
                     bh + ((size_t)(pc * 128 + r)) * DIM + seg * 8);
            }
            cp_commit();
        }
    }

    // ---- quad merge: row best / margin / candidate dump ----
    const int g = lane >> 2;
    #pragma unroll
    for (int h = 0; h < 2; h++) {
        uint32_t* K = h ? K1 : K0;
        int row = Rb + 8 * h + g;
        uint32_t bs = K[0];
        bs = umax(bs, __shfl_xor_sync(0xffffffffu, bs, 1));
        bs = umax(bs, __shfl_xor_sync(0xffffffffu, bs, 2));
        uint32_t sc = (K[0] == bs) ? K[1] : K[0];
        sc = umax(sc, __shfl_xor_sync(0xffffffffu, sc, 1));
        sc = umax(sc, __shfl_xor_sync(0xffffffffu, sc, 2));
        cand[row * 8 + 2 * c]     = (uint16_t)(1023u - (K[0] & 1023u));
        cand[row * 8 + 2 * c + 1] = (uint16_t)(1023u - (K[1] & 1023u));
        if (c == 0) {
            isw[row] = (int)(1023u - (bs & 1023u));
            float mf = __uint_as_float(bs & 0xFFFFFC00u)
                     - __uint_as_float(sc & 0xFFFFFC00u);
            if (mf < THRESH) { int p = atomicAdd(cnt, 1); list[p] = row; }
        }
    }
    __syncthreads();

    // ---- fp64 rescue of tight rows (8 candidates each, warp per row) ----
    int nflag = *cnt;
    for (int e = wid; e < nflag; e += 8) {
        int row = list[e];
        double scv = -1e300; int kk = 0x7fffffff;
        if (lane < 8) {
            kk = (int)cand[row * 8 + lane];
            float rn = rnsm[row];
            const float* cp = g_cnf + (size_t)kk * DIM;
            const float* xr = x + (size_t)(row0 + row) * DIM;
            double d0 = 0, d1 = 0, d2 = 0, d3 = 0;
            #pragma unroll
            for (int j = 0; j < DIM; j += 4) {
                d0 += (double)(xr[j]     / rn) * (double)cp[j];
                d1 += (double)(xr[j + 1] / rn) * (double)cp[j + 1];
                d2 += (double)(xr[j + 2] / rn) * (double)cp[j + 2];
                d3 += (double)(xr[j + 3] / rn) * (double)cp[j + 3];
            }
            scv = ((d0 + d1) + (d2 + d3)) - g_biasd[kk];
        }
        #pragma unroll
        for (int off = 1; off <= 8; off <<= 1) {
            double os = __shfl_xor_sync(0xffffffffu, scv, off);
            int    oi = __shfl_xor_sync(0xffffffffu, kk, off);
            if (os > scv || (os == scv && oi < kk)) { scv = os; kk = oi; }
        }
        if (lane == 0) isw[row] = kk;
    }
    __syncthreads();

    // ---- outputs: STE quantized + indices + partial SSE ----
    const float4* xg4 = (const float4*)(x + (size_t)row0 * DIM);
    float4*       og4 = (float4*)(out + (size_t)row0 * DIM);
    float sse = 0.f;
    #pragma unroll
    for (int i = 0; i < 8; i++) {
        int e4 = tid + i * 256;                // 0..2047 float4
        int r = e4 >> 4, c4 = e4 & 15;
        int k = isw[r];
        float4 xv = xg4[e4];
        float4 q  = *(const float4*)(cb + (size_t)k * DIM + c4 * 4);
        float4 o; float d;
        d = q.x - xv.x; sse += d * d; o.x = xv.x + d;
        d = q.y - xv.y; sse += d * d; o.y = xv.y + d;
        d = q.z - xv.z; sse += d * d; o.z = xv.z + d;
        d = q.w - xv.w; sse += d * d; o.w = xv.w + d;
        og4[e4] = o;
    }
    if (tid < 128) out[(size_t)NQ + 2 + row0 + tid] = (float)isw[tid];

    #pragma unroll
    for (int o = 16; o > 0; o >>= 1) sse += __shfl_xor_sync(0xffffffffu, sse, o);
    if (lane == 0) red[wid] = sse;
    __syncthreads();
    if (tid == 0) {
        float t = 0.f;
        #pragma unroll
        for (int w = 0; w < 8; w++) t += red[w];
        g_partials[blockIdx.x] = t;
    }
}

// ============================================================================
// Kernel 3: reduce partials -> both losses
// ============================================================================
__global__ void vq_fin(float* __restrict__ out) {
    __shared__ float red[8];
    int tid = threadIdx.x;
    float s = 0.f;
    #pragma unroll
    for (int i = 0; i < 8; i++) s += g_partials[tid + i * 256];
    #pragma unroll
    for (int o = 16; o > 0; o >>= 1) s += __shfl_xor_sync(0xffffffffu, s, o);
    if ((tid & 31) == 0) red[tid >> 5] = s;
    __syncthreads();
    if (tid == 0) {
        float t = 0.f;
        #pragma unroll
        for (int w = 0; w < 8; w++) t += red[w];
        float loss = t / 16777216.0f;
        out[NQ]     = loss;   // codebook_loss
        out[NQ + 1] = loss;   // commitment_loss
    }
}

// ============================================================================
extern "C" void kernel_launch(void* const* d_in, const int* in_sizes, int n_in,
                              void* d_out, int out_size) {
    const float* x;
    const float* cb;
    if (in_sizes[0] == NROWS * DIM) {
        x  = (const float*)d_in[0];
        cb = (const float*)d_in[1];
    } else {
        x  = (const float*)d_in[1];
        cb = (const float*)d_in[0];
    }
    float* out = (float*)d_out;

    cudaFuncSetAttribute(vq_main, cudaFuncAttributeMaxDynamicSharedMemorySize, SM_TOTAL);

    vq_prep<<<128, 256>>>(cb);
    vq_main<<<TILES, 256, SM_TOTAL>>>(x, cb, out);
    vq_fin<<<1, 256>>>(out);
}